// round 3
// baseline (speedup 1.0000x reference)
#include <cuda_runtime.h>
#include <cstdint>

// Problem constants (static per reference)
#define BB    8
#define NNODE 384
#define FF    64
#define TT    192
#define NSRC  383      // T + TAU - 1
#define NROWS (5*BB*TT)   // S*B*192 = 7680 argmax rows

typedef unsigned long long ull;

// ---------------- device scratch (no allocs allowed) ----------------
__device__ float g_P[BB*NNODE*FF];        // nodes @ w1_top + b1  (sink half)
__device__ float g_Q[BB*NNODE*FF];        // nodes @ w1_bot       (src half)
__device__ float g_logits[BB*TT*NSRC];    // per-edge logits, dense (b, i, c)

// ---------------- helpers ----------------
__device__ __forceinline__ void fma2(ull &d, ull a, ull b) {
    // paired fp32 FMA (sm_100+): d.lo += a.lo*b.lo; d.hi += a.hi*b.hi
    asm("fma.rn.f32x2 %0, %1, %2, %0;" : "+l"(d) : "l"(a), "l"(b));
}
__device__ __forceinline__ float2 unpack2(ull v) {
    float2 r;
    asm("mov.b64 {%0, %1}, %2;" : "=f"(r.x), "=f"(r.y) : "l"(v));
    return r;
}
__device__ __forceinline__ float warp_sum(float v) {
    #pragma unroll
    for (int o = 16; o; o >>= 1) v += __shfl_xor_sync(0xffffffffu, v, o);
    return v;
}

// ---------------- K1: factor layer 1 per-node ----------------
// P[b,n,f] = b1[f] + sum_k nodes[b,n,k] * w1[k,f]
// Q[b,n,f] =         sum_k nodes[b,n,k] * w1[64+k,f]
__global__ void k_precompute(const float* __restrict__ nodes,
                             const float* __restrict__ w1,
                             const float* __restrict__ b1)
{
    __shared__ float w1s[128*64];
    __shared__ float nds[4][64];
    int tid = threadIdx.x;
    for (int idx = tid; idx < 128*64; idx += 256) w1s[idx] = w1[idx];
    __syncthreads();
    int f = tid & 63, slot = tid >> 6;
    int row0 = blockIdx.x * 32;                 // 96 blocks * 32 rows = 3072
    for (int r = 0; r < 32; r += 4) {
        int row = row0 + r + slot;
        nds[slot][f] = nodes[row*64 + f];
        __syncthreads();
        float accp = b1[f], accq = 0.f;
        #pragma unroll
        for (int k = 0; k < 64; k++) {
            float nv = nds[slot][k];
            accp = fmaf(nv, w1s[k*64 + f],       accp);
            accq = fmaf(nv, w1s[(64+k)*64 + f],  accq);
        }
        g_P[row*64 + f] = accp;
        g_Q[row*64 + f] = accq;
        __syncthreads();
    }
}

// ---------------- K2: fused edge MLP -> logits ----------------
// Block = (chunk cx, sink row i, batch b). 128 edges/block, 256 threads.
// Warp owns 16 edges end-to-end: LN1 -> smem H1 slice -> f32x2 GEMM (j = lane, lane+32,
// k packed in pairs) -> LN2 -> logit.
#define SMEM_FLOATS (8192 + 4096 + 320)
__global__ void __launch_bounds__(256, 2) k_edges(
    const float* __restrict__ w2,  const float* __restrict__ b2,
    const float* __restrict__ g2,  const float* __restrict__ be2,
    const float* __restrict__ w3,  const float* __restrict__ b3,
    const float* __restrict__ g1,  const float* __restrict__ be1)
{
    extern __shared__ float smem[];
    float* H1s   = smem;             // [128][64]
    float* W2pf  = smem + 8192;      // [32][64] float2 (k-pair, j)
    float* sp_p  = smem + 8192 + 4096;  // 64
    float* sp_b2 = sp_p  + 64;
    float* sp_g2 = sp_b2 + 64;
    float* sp_be2= sp_g2 + 64;
    float* sp_w3 = sp_be2+ 64;

    int i = blockIdx.y, b = blockIdx.z;
    int sink = 192 + i;
    int L = sink;                       // valid sources: c in [0, sink)
    int c_base = blockIdx.x * 128;
    if (c_base >= L) return;            // uniform early exit (before any sync)

    int tid = threadIdx.x;
    // phase 0: stage w2 (k-pair interleaved) + small params
    float2* W2p = (float2*)W2pf;
    for (int idx = tid; idx < 2048; idx += 256) {
        int k2 = idx >> 6, j = idx & 63;
        W2p[idx] = make_float2(w2[(2*k2)*64 + j], w2[(2*k2+1)*64 + j]);
    }
    if (tid < 64) {
        sp_p[tid]  = g_P[(b*NNODE + sink)*64 + tid];
        sp_b2[tid] = b2[tid];
        sp_g2[tid] = g2[tid];
        sp_be2[tid]= be2[tid];
        sp_w3[tid] = w3[tid];
    }
    __syncthreads();

    int lane = tid & 31;
    int w    = tid >> 5;
    int e_lo = w * 16;

    // ---- phase 1: H1 = LN(relu(P[sink] + Q[src])) for this warp's 16 edges ----
    {
        float2 p2  = *(const float2*)&sp_p[2*lane];
        float2 g1v = __ldg((const float2*)&g1[2*lane]);
        float2 be1v= __ldg((const float2*)&be1[2*lane]);
        #pragma unroll 4
        for (int e = e_lo; e < e_lo + 16; e++) {
            int c = c_base + e;                       // always < 384: safe read
            float2 q2 = __ldg((const float2*)&g_Q[((b*NNODE) + c)*64 + 2*lane]);
            float x0 = fmaxf(p2.x + q2.x, 0.f);
            float x1 = fmaxf(p2.y + q2.y, 0.f);
            float mu = warp_sum(x0 + x1) * (1.f/64.f);
            float d0 = x0 - mu, d1 = x1 - mu;
            float v  = warp_sum(d0*d0 + d1*d1) * (1.f/64.f);
            float rstd = 1.f / sqrtf(v + 1e-5f);
            float h0 = fmaf(d0*rstd, g1v.x, be1v.x);
            float h1 = fmaf(d1*rstd, g1v.y, be1v.y);
            *(float2*)&H1s[e*64 + 2*lane] = make_float2(h0, h1);
        }
    }
    __syncwarp();

    // ---- phase 2+3: f32x2 GEMM (64x64) + LN2 + logit, in-warp ----
    {
        const ull* w2u = (const ull*)W2pf;            // [k2*64 + j]
        float b2a = sp_b2[lane],  b2b = sp_b2[lane+32];
        float g2a = sp_g2[lane],  g2b = sp_g2[lane+32];
        float be2a= sp_be2[lane], be2b= sp_be2[lane+32];
        float w3a = sp_w3[lane],  w3b = sp_w3[lane+32];
        float b3v = __ldg(&b3[0]);
        float* lrow = g_logits + (b*TT + i)*NSRC;

        for (int pass = 0; pass < 2; pass++) {
            int e0 = e_lo + pass*8;
            ull accA[8], accB[8];                     // j=lane / j=lane+32, k-paired
            #pragma unroll
            for (int e = 0; e < 8; e++) { accA[e] = 0ull; accB[e] = 0ull; }

            #pragma unroll
            for (int k2 = 0; k2 < 32; k2 += 2) {
                ull wA0 = w2u[ k2   *64 + lane];
                ull wB0 = w2u[(k2+1)*64 + lane];
                ull wA1 = w2u[ k2   *64 + lane + 32];
                ull wB1 = w2u[(k2+1)*64 + lane + 32];
                #pragma unroll
                for (int e = 0; e < 8; e++) {
                    const ulonglong2 hv =
                        *(const ulonglong2*)&H1s[(e0+e)*64 + 2*k2];  // bcast LDS.128
                    fma2(accA[e], hv.x, wA0);
                    fma2(accA[e], hv.y, wB0);
                    fma2(accB[e], hv.x, wA1);
                    fma2(accB[e], hv.y, wB1);
                }
            }
            #pragma unroll
            for (int e = 0; e < 8; e++) {
                float2 ta = unpack2(accA[e]);
                float2 tb = unpack2(accB[e]);
                float x0 = fmaxf(ta.x + ta.y + b2a, 0.f);  // relu(h1@w2 + b2)
                float x1 = fmaxf(tb.x + tb.y + b2b, 0.f);
                float mu = warp_sum(x0 + x1) * (1.f/64.f);
                float d0 = x0 - mu, d1 = x1 - mu;
                float v  = warp_sum(d0*d0 + d1*d1) * (1.f/64.f);
                float rstd = 1.f / sqrtf(v + 1e-5f);
                float h0 = fmaf(d0*rstd, g2a, be2a);
                float h1 = fmaf(d1*rstd, g2b, be2b);
                float part = warp_sum(h0*w3a + h1*w3b);
                int c = c_base + e0 + e;
                if (lane == 0 && c < L) lrow[c] = part + b3v;
            }
        }
    }
}

// ---------------- K3: zero the output grid ----------------
__global__ void k_zero(float4* __restrict__ out, int n4)
{
    int idx = blockIdx.x * blockDim.x + threadIdx.x;
    int stride = gridDim.x * blockDim.x;
    float4 z = make_float4(0.f, 0.f, 0.f, 0.f);
    for (; idx < n4; idx += stride) out[idx] = z;
}

// ---------------- K4: gumbel argmax + scatter 1.0 ----------------
// One warp per (s,b,i) row; argmax over valid c of logits + gumbel
// (softmax is monotone so argmax(y_soft) == argmax(logits+gumbel);
//  first-occurrence tie-break matches jnp.argmax).
__global__ void k_argmax(const float* __restrict__ gumbel, float* __restrict__ out)
{
    int row = blockIdx.x * 8 + (threadIdx.x >> 5);
    if (row >= NROWS) return;
    int lane = threadIdx.x & 31;
    int i  = row % TT;
    int sb = row / TT;          // s*8 + b
    int b  = sb & 7;
    int L  = 192 + i;

    const float* lg = g_logits + (size_t)((b*TT + i)) * NSRC;
    const float* gb = gumbel   + (size_t)row * NSRC;

    float best = -__int_as_float(0x7f800000);   // -inf
    int bidx = 0;
    for (int c = lane; c < L; c += 32) {
        float v = lg[c] + gb[c];
        if (v > best) { best = v; bidx = c; }   // keeps earliest c per lane
    }
    #pragma unroll
    for (int o = 16; o; o >>= 1) {
        float ov = __shfl_xor_sync(0xffffffffu, best, o);
        int   oi = __shfl_xor_sync(0xffffffffu, bidx, o);
        if (ov > best || (ov == best && oi < bidx)) { best = ov; bidx = oi; }
    }
    if (lane == 0)
        out[((size_t)(b*NNODE) + 192 + i) * NNODE + bidx] = 1.0f;   // exact 1.0 per ref
}

// ---------------- launch ----------------
extern "C" void kernel_launch(void* const* d_in, const int* in_sizes, int n_in,
                              void* d_out, int out_size)
{
    const float* nodes = (const float*)d_in[0];
    const float* w1    = (const float*)d_in[1];
    const float* b1    = (const float*)d_in[2];
    const float* g1    = (const float*)d_in[3];
    const float* be1   = (const float*)d_in[4];
    const float* w2    = (const float*)d_in[5];
    const float* b2    = (const float*)d_in[6];
    const float* g2    = (const float*)d_in[7];
    const float* be2   = (const float*)d_in[8];
    const float* w3    = (const float*)d_in[9];
    const float* b3    = (const float*)d_in[10];
    const float* gum   = (const float*)d_in[11];
    // d_in[12..14] (batch_idx/sink_idx/source_idx) are static structure; unused.
    float* out = (float*)d_out;

    const int smem_bytes = SMEM_FLOATS * (int)sizeof(float);   // 50,432 B
    cudaFuncSetAttribute(k_edges, cudaFuncAttributeMaxDynamicSharedMemorySize, smem_bytes);

    k_precompute<<<96, 256>>>(nodes, w1, b1);
    k_edges<<<dim3(3, TT, BB), 256, smem_bytes>>>(w2, b2, g2, be2, w3, b3, g1, be1);

    int n4 = out_size / 4;                                     // 294,912 float4
    k_zero<<<512, 256>>>((float4*)out, n4);
    k_argmax<<<NROWS / 8, 256>>>(gum, out);
}